// round 5
// baseline (speedup 1.0000x reference)
#include <cuda_runtime.h>
#include <math.h>
#include <stdint.h>

#define Bv 2
#define Tv 2048
#define Cv 768
#define Hv 12
#define BTv 4096
typedef unsigned long long ull;

__device__ float g_Q[Bv*Hv*Tv*64];
__device__ float g_K[Bv*Hv*Tv*64];
__device__ float g_V[Bv*Hv*Tv*64];
__device__ float g_Y[BTv*Cv];

__device__ __forceinline__ ull pk2(float lo, float hi) {
    ull r; asm("mov.b64 %0, {%1, %2};" : "=l"(r) : "f"(lo), "f"(hi)); return r;
}
__device__ __forceinline__ void fma2(ull& d, ull a, ull b) {
    asm("fma.rn.f32x2 %0, %1, %2, %3;" : "=l"(d) : "l"(a), "l"(b), "l"(d));
}
__device__ __forceinline__ void upk(ull p, float& lo, float& hi) {
    asm("mov.b64 {%0, %1}, %2;" : "=f"(lo), "=f"(hi) : "l"(p));
}
__device__ __forceinline__ unsigned int saddr(const void* p) {
    return (unsigned int)__cvta_generic_to_shared(p);
}
__device__ __forceinline__ void cpa16(unsigned int dst, const void* src) {
    asm volatile("cp.async.cg.shared.global [%0], [%1], 16;" :: "r"(dst), "l"(src));
}
__device__ __forceinline__ void cpa_commit() { asm volatile("cp.async.commit_group;"); }
template<int N> __device__ __forceinline__ void cpa_wait() {
    asm volatile("cp.async.wait_group %0;" :: "n"(N));
}

// ---------------------------------------------------------------------------
// GEMM (unchanged from R4): BM=128 BN=128 BK=16, 8x8 microtile via f32x2.
// ---------------------------------------------------------------------------
__global__ __launch_bounds__(256, 2) void gemm_kernel(
    const float* __restrict__ A, const float* __restrict__ Wq,
    const float* __restrict__ Wk, const float* __restrict__ Wv,
    const float* __restrict__ qm, float* __restrict__ outp, int mode_base)
{
    __shared__ float As[2][16*132];
    __shared__ float Bs[2][16*132];

    const int mode = mode_base + blockIdx.z;
    const float* W  = (mode == 0) ? Wq : (mode == 1) ? Wk : (mode == 2) ? Wv : Wq;
    const float* Ap = (mode == 3) ? (const float*)g_Y : A;

    const int tid = threadIdx.x;
    const int ty = tid >> 4, tx = tid & 15;
    const int m0 = blockIdx.x * 128, n0 = blockIdx.y * 128;
    const int arow = tid >> 2, ac4 = tid & 3;
    const int brow = tid >> 5, bc4 = tid & 31;
    const float* aG = Ap + (size_t)(m0 + arow) * 768 + ac4 * 4;
    const float* bG = W + (size_t)brow * 768 + n0 + bc4 * 4;

    ull acc2[8][4];
    #pragma unroll
    for (int r = 0; r < 8; r++)
        #pragma unroll
        for (int c = 0; c < 4; c++) acc2[r][c] = 0ull;

    float4 ra0 = *(const float4*)aG;
    float4 ra1 = *(const float4*)(aG + (size_t)64 * 768);
    float4 rb0 = *(const float4*)bG;
    float4 rb1 = *(const float4*)(bG + (size_t)8 * 768);

    #pragma unroll 1
    for (int kt = 0; kt < 48; kt++) {
        {
            float* as = As[kt & 1]; float* bs = Bs[kt & 1];
            as[(ac4*4+0)*132 + arow] = ra0.x; as[(ac4*4+1)*132 + arow] = ra0.y;
            as[(ac4*4+2)*132 + arow] = ra0.z; as[(ac4*4+3)*132 + arow] = ra0.w;
            as[(ac4*4+0)*132 + arow+64] = ra1.x; as[(ac4*4+1)*132 + arow+64] = ra1.y;
            as[(ac4*4+2)*132 + arow+64] = ra1.z; as[(ac4*4+3)*132 + arow+64] = ra1.w;
            *(float4*)&bs[brow*132 + bc4*4] = rb0;
            *(float4*)&bs[(brow+8)*132 + bc4*4] = rb1;
        }
        __syncthreads();
        if (kt < 47) {
            ra0 = *(const float4*)(aG + (kt+1)*16);
            ra1 = *(const float4*)(aG + (size_t)64*768 + (kt+1)*16);
            rb0 = *(const float4*)(bG + (size_t)(kt+1)*16*768);
            rb1 = *(const float4*)(bG + (size_t)(kt+1)*16*768 + (size_t)8*768);
        }
        const float* as = As[kt & 1]; const float* bs = Bs[kt & 1];
        #pragma unroll
        for (int kk = 0; kk < 16; kk++) {
            float4 a0 = *(const float4*)&as[kk*132 + ty*8];
            float4 a1 = *(const float4*)&as[kk*132 + ty*8 + 4];
            ulonglong2 b0 = *(const ulonglong2*)&bs[kk*132 + tx*4];
            ulonglong2 b1 = *(const ulonglong2*)&bs[kk*132 + 64 + tx*4];
            ull ad[8] = { pk2(a0.x,a0.x), pk2(a0.y,a0.y), pk2(a0.z,a0.z), pk2(a0.w,a0.w),
                          pk2(a1.x,a1.x), pk2(a1.y,a1.y), pk2(a1.z,a1.z), pk2(a1.w,a1.w) };
            #pragma unroll
            for (int r = 0; r < 8; r++) {
                fma2(acc2[r][0], ad[r], b0.x);
                fma2(acc2[r][1], ad[r], b0.y);
                fma2(acc2[r][2], ad[r], b1.x);
                fma2(acc2[r][3], ad[r], b1.y);
            }
        }
        __syncthreads();
    }

    float accf[8][8];
    #pragma unroll
    for (int r = 0; r < 8; r++) {
        upk(acc2[r][0], accf[r][0], accf[r][1]);
        upk(acc2[r][1], accf[r][2], accf[r][3]);
        upk(acc2[r][2], accf[r][4], accf[r][5]);
        upk(acc2[r][3], accf[r][6], accf[r][7]);
    }

    if (mode == 3) {
        #pragma unroll
        for (int r = 0; r < 8; r++) {
            int row = m0 + ty*8 + r;
            *(float4*)(outp + (size_t)row*768 + n0 + tx*4) =
                make_float4(accf[r][0], accf[r][1], accf[r][2], accf[r][3]);
            *(float4*)(outp + (size_t)row*768 + n0 + 64 + tx*4) =
                make_float4(accf[r][4], accf[r][5], accf[r][6], accf[r][7]);
        }
    } else {
        float* dst = (mode == 0) ? g_Q : (mode == 1) ? g_K : g_V;
        const int h0 = n0 >> 6, d0 = tx*4;
        float s0 = 1.f, s1 = 1.f, s2 = 1.f, s3 = 1.f;
        if (mode == 0) {
            const float LT = 7.6246189861593985f;
            s0 = LT*qm[d0]; s1 = LT*qm[d0+1]; s2 = LT*qm[d0+2]; s3 = LT*qm[d0+3];
        }
        #pragma unroll
        for (int r = 0; r < 8; r++) {
            int row = m0 + ty*8 + r;
            int bb = row >> 11, t = row & 2047;
            size_t p0 = ((size_t)(bb*Hv + h0)*Tv + t)*64 + d0;
            size_t p1 = ((size_t)(bb*Hv + h0 + 1)*Tv + t)*64 + d0;
            *(float4*)(dst + p0) = make_float4(accf[r][0]*s0, accf[r][1]*s1,
                                               accf[r][2]*s2, accf[r][3]*s3);
            *(float4*)(dst + p1) = make_float4(accf[r][4]*s0, accf[r][5]*s1,
                                               accf[r][6]*s2, accf[r][7]*s3);
        }
    }
}

// ---------------------------------------------------------------------------
// Attention v2: natural [row][d] smem (stride 68), cp.async 3-stage K ring,
// 1 sync/tile, f32x2 packed along d (score = lo+hi), no transposes/STS.
// Thread (qy,kx): queries qy*4..+3, keys {kx,kx+16,kx+32,kx+48} per tile.
// ---------------------------------------------------------------------------
#define AST 68   // row stride (floats): 272B, 16B-aligned chunks
__global__ __launch_bounds__(256) void attn_kernel()
{
    extern __shared__ float sm[];
    float* Qt = sm;                 // [64][AST]
    float* Kb[3] = { sm + 64*AST, sm + 2*64*AST, sm + 3*64*AST };

    const int tid = threadIdx.x;
    const int qy = tid >> 4, kx = tid & 15;
    const int qt = 31 - (int)blockIdx.x;
    const int h = blockIdx.y, b = blockIdx.z;
    const size_t bh = ((size_t)(b*Hv + h)) * Tv * 64;

    const int lrow = tid >> 4;      // 0..15 (+16 per it)
    const int ld4  = tid & 15;

    // group 0: Q tile + K tile 0
    #pragma unroll
    for (int it = 0; it < 4; it++) {
        int row = it*16 + lrow;
        cpa16(saddr(Qt + row*AST + ld4*4), g_Q + bh + (size_t)(qt*64 + row)*64 + ld4*4);
        cpa16(saddr(Kb[0] + row*AST + ld4*4), g_K + bh + (size_t)row*64 + ld4*4);
    }
    cpa_commit();
    // group 1: K tile 1 (clamped)
    {
        int t1 = (qt >= 1) ? 1 : 0;
        #pragma unroll
        for (int it = 0; it < 4; it++) {
            int row = it*16 + lrow;
            cpa16(saddr(Kb[1] + row*AST + ld4*4), g_K + bh + (size_t)(t1*64 + row)*64 + ld4*4);
        }
        cpa_commit();
    }

    float tv[4][4]; int ti[4][4];
    #pragma unroll
    for (int q = 0; q < 4; q++)
        #pragma unroll
        for (int m = 0; m < 4; m++) { tv[q][m] = -3.0e38f; ti[q][m] = 0; }

    for (int kt = 0; kt <= qt; kt++) {
        cpa_wait<1>();          // K_kt resident
        __syncthreads();        // visible to all; prev compute done
        if (kt + 2 <= qt) {     // prefetch K_{kt+2}
            float* nb = Kb[(kt+2)%3];
            #pragma unroll
            for (int it = 0; it < 4; it++) {
                int row = it*16 + lrow;
                cpa16(saddr(nb + row*AST + ld4*4),
                      g_K + bh + (size_t)((kt+2)*64 + row)*64 + ld4*4);
            }
        }
        cpa_commit();           // always, to keep group counting uniform

        const float* kb = Kb[kt%3];
        ull acc2[4][4];
        #pragma unroll
        for (int q = 0; q < 4; q++)
            #pragma unroll
            for (int j = 0; j < 4; j++) acc2[q][j] = 0ull;

        #pragma unroll
        for (int d4 = 0; d4 < 16; d4++) {
            ulonglong2 qv[4], kv[4];
            #pragma unroll
            for (int q = 0; q < 4; q++)
                qv[q] = *(const ulonglong2*)(Qt + (qy*4+q)*AST + d4*4);
            #pragma unroll
            for (int j = 0; j < 4; j++)
                kv[j] = *(const ulonglong2*)(kb + (kx + j*16)*AST + d4*4);
            #pragma unroll
            for (int q = 0; q < 4; q++)
                #pragma unroll
                for (int j = 0; j < 4; j++) {
                    fma2(acc2[q][j], qv[q].x, kv[j].x);
                    fma2(acc2[q][j], qv[q].y, kv[j].y);
                }
        }

        #pragma unroll
        for (int q = 0; q < 4; q++) {
            int iglob = qt*64 + qy*4 + q;
            #pragma unroll
            for (int j = 0; j < 4; j++) {
                int jglob = kt*64 + kx + j*16;
                float lo, hi; upk(acc2[q][j], lo, hi);
                float s = (lo + hi) * 0.125f;
                if (jglob <= iglob && s > tv[q][3]) {
                    if (s > tv[q][1]) {
                        tv[q][3] = tv[q][2]; ti[q][3] = ti[q][2];
                        tv[q][2] = tv[q][1]; ti[q][2] = ti[q][1];
                        if (s > tv[q][0]) {
                            tv[q][1] = tv[q][0]; ti[q][1] = ti[q][0];
                            tv[q][0] = s; ti[q][0] = jglob;
                        } else { tv[q][1] = s; ti[q][1] = jglob; }
                    } else {
                        if (s > tv[q][2]) {
                            tv[q][3] = tv[q][2]; ti[q][3] = ti[q][2];
                            tv[q][2] = s; ti[q][2] = jglob;
                        } else { tv[q][3] = s; ti[q][3] = jglob; }
                    }
                }
            }
        }
    }

    #pragma unroll
    for (int msk = 1; msk <= 8; msk <<= 1) {
        #pragma unroll
        for (int q = 0; q < 4; q++) {
            float bvv[4]; int bii[4];
            #pragma unroll
            for (int r = 0; r < 4; r++) {
                bvv[r] = __shfl_xor_sync(0xffffffffu, tv[q][r], msk);
                bii[r] = __shfl_xor_sync(0xffffffffu, ti[q][r], msk);
            }
            float mv[4]; int mi[4];
            #pragma unroll
            for (int r = 0; r < 4; r++) {
                bool ta = tv[q][r] >= bvv[3-r];
                mv[r] = ta ? tv[q][r] : bvv[3-r];
                mi[r] = ta ? ti[q][r] : bii[3-r];
            }
            #define CEPAIR(x, y) do { if (mv[x] < mv[y]) { float tf=mv[x];mv[x]=mv[y];mv[y]=tf; int tn=mi[x];mi[x]=mi[y];mi[y]=tn; } } while (0)
            CEPAIR(0,2); CEPAIR(1,3); CEPAIR(0,1); CEPAIR(2,3);
            #undef CEPAIR
            #pragma unroll
            for (int r = 0; r < 4; r++) { tv[q][r] = mv[r]; ti[q][r] = mi[r]; }
        }
    }

    #pragma unroll
    for (int q = 0; q < 4; q++) {
        int iglob = qt*64 + qy*4 + q;
        int nz = Tv - (iglob + 1);
        int p = (tv[q][0] > 0.f) + (tv[q][1] > 0.f) + (tv[q][2] > 0.f) + (tv[q][3] > 0.f);
        float kth;
        if (p >= 4) kth = tv[q][3];
        else if (nz >= 4 - p) kth = 0.0f;
        else {
            int ix = 3 - nz;
            kth = (ix == 0) ? tv[q][0] : (ix == 1) ? tv[q][1] : (ix == 2) ? tv[q][2] : tv[q][3];
        }
        float a0 = 0.f, a1 = 0.f, a2 = 0.f, a3 = 0.f;
        #pragma unroll
        for (int m = 0; m < 4; m++) {
            float val = tv[q][m];
            if (val >= kth && val > -1.0e37f) {
                float w = tanhf(val);
                float4 vv = *(const float4*)(g_V + bh + (size_t)ti[q][m]*64 + kx*4);
                a0 += w*vv.x; a1 += w*vv.y; a2 += w*vv.z; a3 += w*vv.w;
            }
        }
        *(float4*)(g_Y + (size_t)(b*Tv + iglob)*Cv + h*64 + kx*4) =
            make_float4(a0, a1, a2, a3);
    }
}

extern "C" void kernel_launch(void* const* d_in, const int* in_sizes, int n_in,
                              void* d_out, int out_size)
{
    (void)in_sizes; (void)n_in; (void)out_size;
    const float* x  = (const float*)d_in[0];
    const float* Wq = (const float*)d_in[1];
    const float* Wk = (const float*)d_in[2];
    const float* Wv = (const float*)d_in[3];
    const float* Wp = (const float*)d_in[4];
    const float* qm = (const float*)d_in[5];
    float* out = (float*)d_out;

    const int attn_smem = 4 * 64 * AST * 4;   // Qt + 3 K buffers = 69632 B
    cudaFuncSetAttribute(attn_kernel, cudaFuncAttributeMaxDynamicSharedMemorySize, attn_smem);

    dim3 blk(256);
    gemm_kernel<<<dim3(32, 6, 3), blk>>>(x, Wq, Wk, Wv, qm, nullptr, 0);
    attn_kernel<<<dim3(32, 12, 2), blk, attn_smem>>>();
    gemm_kernel<<<dim3(32, 6, 1), blk>>>(nullptr, Wp, Wp, Wp, qm, out, 3);
}